// round 1
// baseline (speedup 1.0000x reference)
#include <cuda_runtime.h>
#include <math.h>
#include <stdint.h>

// ---------------------------------------------------------------------------
// GPT-2 small forward:  B=2, S=1024, L=4, H=12, E=768, D=64, V=50257
// ---------------------------------------------------------------------------
#define BB 2
#define SS 1024
#define LL 4
#define HH 12
#define EE 768
#define VV 50257
#define DD 64
#define MM (BB*SS)          // 2048 token rows

// Scratch (device globals: allocation-free rule)
__device__ float g_X  [MM * EE];        // residual stream
__device__ float g_H  [MM * EE];        // LN output
__device__ float g_QKV[MM * 3 * EE];    // qkv
__device__ float g_ATT[MM * EE];        // attention output
__device__ float g_FC [MM * 4 * EE];    // MLP hidden

// ---------------------------------------------------------------------------
// Embedding: x = wte[token] + wpe[s]
// ---------------------------------------------------------------------------
__global__ void embed_k(const int* __restrict__ tok,
                        const float* __restrict__ wte,
                        const float* __restrict__ wpe,
                        float* __restrict__ X)
{
    int row = blockIdx.x;              // 0..2047
    int s   = row & (SS - 1);
    int t   = tok[row];
    const float* we = wte + (size_t)t * EE;
    const float* wp = wpe + (size_t)s * EE;
    float* xr = X + (size_t)row * EE;
    for (int e = threadIdx.x; e < EE; e += blockDim.x)
        xr[e] = we[e] + wp[e];
}

// ---------------------------------------------------------------------------
// LayerNorm: one block (256 threads) per row of 768
// ---------------------------------------------------------------------------
__global__ __launch_bounds__(256) void ln_k(const float* __restrict__ X,
                                            const float* __restrict__ gam,
                                            const float* __restrict__ bet,
                                            float* __restrict__ O)
{
    __shared__ float s1[8], s2[8];
    int row = blockIdx.x, tid = threadIdx.x;
    const float* xr = X + (size_t)row * EE;
    float v[3];
    float sum = 0.f, sq = 0.f;
#pragma unroll
    for (int k = 0; k < 3; k++) {
        v[k] = xr[tid + k * 256];
        sum += v[k];
        sq  += v[k] * v[k];
    }
#pragma unroll
    for (int o = 16; o > 0; o >>= 1) {
        sum += __shfl_xor_sync(0xffffffffu, sum, o);
        sq  += __shfl_xor_sync(0xffffffffu, sq,  o);
    }
    if ((tid & 31) == 0) { s1[tid >> 5] = sum; s2[tid >> 5] = sq; }
    __syncthreads();
    sum = 0.f; sq = 0.f;
#pragma unroll
    for (int i = 0; i < 8; i++) { sum += s1[i]; sq += s2[i]; }
    const float inv_n = 1.0f / (float)EE;
    float mu  = sum * inv_n;
    float var = sq * inv_n - mu * mu;
    float rs  = rsqrtf(var + 1e-5f);
    float* orow = O + (size_t)row * EE;
#pragma unroll
    for (int k = 0; k < 3; k++) {
        int e = tid + k * 256;
        orow[e] = (v[k] - mu) * rs * gam[e] + bet[e];
    }
}

// ---------------------------------------------------------------------------
// SGEMM: C[M,N] = A[M,K] @ B[K,N] (+bias) (+GELU) (+residual)
// 128x128 block tile, BK=8, 8x8 per-thread microtile, 256 threads
// ---------------------------------------------------------------------------
template<bool BIAS, bool GELU, bool RES, bool VECB>
__global__ __launch_bounds__(256) void sgemm_k(const float* __restrict__ A,
                                               const float* __restrict__ Bm,
                                               const float* __restrict__ bias,
                                               const float* __restrict__ res,
                                               float* __restrict__ C,
                                               int M, int N, int K)
{
    const int BK = 8;
    __shared__ float As[BK][128];
    __shared__ float Bs[BK][128];

    int tid = threadIdx.x;
    int bm = blockIdx.y * 128;
    int bn = blockIdx.x * 128;

    int rowA = tid >> 1;            // 0..127
    int colA = (tid & 1) * 4;       // 0 or 4
    int rowB = tid >> 5;            // 0..7
    int colB = (tid & 31) * 4;      // 0..124

    int tr = (tid >> 4) * 8;        // microtile row base
    int tc = (tid & 15) * 8;        // microtile col base

    float acc[8][8];
#pragma unroll
    for (int i = 0; i < 8; i++)
#pragma unroll
        for (int j = 0; j < 8; j++) acc[i][j] = 0.f;

    for (int k0 = 0; k0 < K; k0 += BK) {
        // load A tile (always aligned: K % 4 == 0, M % 128 == 0)
        float4 a4 = *(const float4*)(A + (size_t)(bm + rowA) * K + k0 + colA);
        As[colA + 0][rowA] = a4.x;
        As[colA + 1][rowA] = a4.y;
        As[colA + 2][rowA] = a4.z;
        As[colA + 3][rowA] = a4.w;
        // load B tile
        if (VECB) {
            float4 b4 = *(const float4*)(Bm + (size_t)(k0 + rowB) * N + bn + colB);
            *(float4*)&Bs[rowB][colB] = b4;
        } else {
            const float* brow = Bm + (size_t)(k0 + rowB) * N;
#pragma unroll
            for (int j = 0; j < 4; j++) {
                int n = bn + colB + j;
                Bs[rowB][colB + j] = (n < N) ? brow[n] : 0.f;
            }
        }
        __syncthreads();
#pragma unroll
        for (int kk = 0; kk < BK; kk++) {
            float ra[8], rb[8];
#pragma unroll
            for (int i = 0; i < 8; i++) ra[i] = As[kk][tr + i];
#pragma unroll
            for (int j = 0; j < 8; j++) rb[j] = Bs[kk][tc + j];
#pragma unroll
            for (int i = 0; i < 8; i++)
#pragma unroll
                for (int j = 0; j < 8; j++)
                    acc[i][j] = fmaf(ra[i], rb[j], acc[i][j]);
        }
        __syncthreads();
    }

#pragma unroll
    for (int i = 0; i < 8; i++) {
        int m = bm + tr + i;
#pragma unroll
        for (int j = 0; j < 8; j++) {
            int n = bn + tc + j;
            if (n < N) {
                float vv = acc[i][j];
                if (BIAS) vv += bias[n];
                if (GELU) vv = 0.5f * vv * (1.f + erff(vv * 0.70710678118654752f));
                if (RES)  vv += res[(size_t)m * N + n];
                C[(size_t)m * N + n] = vv;
            }
        }
    }
}

// ---------------------------------------------------------------------------
// Causal attention with online softmax.
// Block = (q_tile=64 queries, head h, batch b); 256 threads.
// K stored transposed in SMEM so score & PV loops vectorize (LDS.128).
// ---------------------------------------------------------------------------
__global__ __launch_bounds__(256) void attn_k(const float* __restrict__ QKV,
                                              float* __restrict__ O)
{
    const int TQ = 64, TK = 32;
    __shared__ float Qs[TQ][DD + 1];      // 64 x 65 (padded, scalar reads)
    __shared__ float Kt[DD][TK];          // 64 x 32 transposed (vector reads)
    __shared__ float Vs[TK][DD];          // 32 x 64 (vector reads)
    __shared__ float Ps[TQ][TK + 1];      // 64 x 33
    __shared__ float red[TQ][4];

    int tid = threadIdx.x;
    int qt = blockIdx.x, h = blockIdx.y, b = blockIdx.z;
    int r  = tid >> 2;                    // query row in tile: 0..63
    int q4 = tid & 3;                     // quad index: 0..3
    int qi = qt * TQ + r;                 // global query index

    const size_t rstride = 3 * EE;
    const float* qkvb = QKV + (size_t)b * SS * rstride;

    // load Q tile
    for (int i = tid; i < TQ * DD; i += 256) {
        int rr = i >> 6, d = i & 63;
        Qs[rr][d] = qkvb[(size_t)(qt * TQ + rr) * rstride + h * DD + d];
    }

    float m = -INFINITY, l = 0.f;
    float o[16];
#pragma unroll
    for (int j = 0; j < 16; j++) o[j] = 0.f;
    const float scale = 0.125f;           // 1/sqrt(64)

    int nkt = (qt + 1) * (TQ / TK);
    for (int kt = 0; kt < nkt; kt++) {
        __syncthreads();                  // protect tiles from prior iter / Q load
        for (int i = tid; i < TK * DD; i += 256) {
            int rr = i >> 6, d = i & 63;
            size_t base = (size_t)(kt * TK + rr) * rstride + h * DD + d;
            Kt[d][rr] = qkvb[EE + base];
            Vs[rr][d] = qkvb[2 * EE + base];
        }
        __syncthreads();

        // --- scores: sc[j] = dot(Q[r], K[c]) over d, c = q4*8+j
        float sc[8];
#pragma unroll
        for (int j = 0; j < 8; j++) sc[j] = 0.f;
#pragma unroll 8
        for (int d = 0; d < DD; d++) {
            float qv = Qs[r][d];
            float4 k0 = *(const float4*)&Kt[d][q4 * 8];
            float4 k1 = *(const float4*)&Kt[d][q4 * 8 + 4];
            sc[0] = fmaf(qv, k0.x, sc[0]);
            sc[1] = fmaf(qv, k0.y, sc[1]);
            sc[2] = fmaf(qv, k0.z, sc[2]);
            sc[3] = fmaf(qv, k0.w, sc[3]);
            sc[4] = fmaf(qv, k1.x, sc[4]);
            sc[5] = fmaf(qv, k1.y, sc[5]);
            sc[6] = fmaf(qv, k1.z, sc[6]);
            sc[7] = fmaf(qv, k1.w, sc[7]);
        }
        float lmax = -INFINITY;
#pragma unroll
        for (int j = 0; j < 8; j++) {
            int kg = kt * TK + q4 * 8 + j;
            sc[j] = (kg <= qi) ? sc[j] * scale : -1e30f;
            lmax = fmaxf(lmax, sc[j]);
        }
        red[r][q4] = lmax;
        __syncthreads();
        float mnew = fmaxf(fmaxf(fmaxf(red[r][0], red[r][1]),
                                 fmaxf(red[r][2], red[r][3])), m);
        __syncthreads();                  // done reading red before reuse

        float lsum = 0.f;
#pragma unroll
        for (int j = 0; j < 8; j++) {
            float p = __expf(sc[j] - mnew);
            Ps[r][q4 * 8 + j] = p;
            lsum += p;
        }
        red[r][q4] = lsum;
        __syncthreads();
        float tsum = red[r][0] + red[r][1] + red[r][2] + red[r][3];
        float fac = __expf(m - mnew);
        l = l * fac + tsum;
        m = mnew;
#pragma unroll
        for (int j = 0; j < 16; j++) o[j] *= fac;

        // --- PV: o[j] += p[c] * V[c][q4*16+j]
#pragma unroll 4
        for (int c = 0; c < TK; c++) {
            float p = Ps[r][c];
            float4 v0 = *(const float4*)&Vs[c][q4 * 16 + 0];
            float4 v1 = *(const float4*)&Vs[c][q4 * 16 + 4];
            float4 v2 = *(const float4*)&Vs[c][q4 * 16 + 8];
            float4 v3 = *(const float4*)&Vs[c][q4 * 16 + 12];
            o[0]  = fmaf(p, v0.x, o[0]);  o[1]  = fmaf(p, v0.y, o[1]);
            o[2]  = fmaf(p, v0.z, o[2]);  o[3]  = fmaf(p, v0.w, o[3]);
            o[4]  = fmaf(p, v1.x, o[4]);  o[5]  = fmaf(p, v1.y, o[5]);
            o[6]  = fmaf(p, v1.z, o[6]);  o[7]  = fmaf(p, v1.w, o[7]);
            o[8]  = fmaf(p, v2.x, o[8]);  o[9]  = fmaf(p, v2.y, o[9]);
            o[10] = fmaf(p, v2.z, o[10]); o[11] = fmaf(p, v2.w, o[11]);
            o[12] = fmaf(p, v3.x, o[12]); o[13] = fmaf(p, v3.y, o[13]);
            o[14] = fmaf(p, v3.z, o[14]); o[15] = fmaf(p, v3.w, o[15]);
        }
    }

    float inv = 1.f / l;
    float* orow = O + ((size_t)b * SS + qi) * EE + h * DD + q4 * 16;
#pragma unroll
    for (int j = 0; j < 16; j++) orow[j] = o[j] * inv;
}

// ---------------------------------------------------------------------------
// Host launcher
// ---------------------------------------------------------------------------
extern "C" void kernel_launch(void* const* d_in, const int* in_sizes, int n_in,
                              void* d_out, int out_size)
{
    const int*   tok    = (const int*)  d_in[0];
    const float* wte    = (const float*)d_in[1];
    const float* wpe    = (const float*)d_in[2];
    const float* ln1_g  = (const float*)d_in[3];
    const float* ln1_b  = (const float*)d_in[4];
    const float* attn_w = (const float*)d_in[5];
    const float* attn_b = (const float*)d_in[6];
    const float* proj_w = (const float*)d_in[7];
    const float* proj_b = (const float*)d_in[8];
    const float* ln2_g  = (const float*)d_in[9];
    const float* ln2_b  = (const float*)d_in[10];
    const float* fc_w   = (const float*)d_in[11];
    const float* fc_b   = (const float*)d_in[12];
    const float* fc2_w  = (const float*)d_in[13];
    const float* fc2_b  = (const float*)d_in[14];
    const float* lnf_g  = (const float*)d_in[15];
    const float* lnf_b  = (const float*)d_in[16];
    const float* lm_w   = (const float*)d_in[17];
    float* out = (float*)d_out;

    float *X, *Hb, *QKV, *ATT, *FC;
    cudaGetSymbolAddress((void**)&X,   g_X);
    cudaGetSymbolAddress((void**)&Hb,  g_H);
    cudaGetSymbolAddress((void**)&QKV, g_QKV);
    cudaGetSymbolAddress((void**)&ATT, g_ATT);
    cudaGetSymbolAddress((void**)&FC,  g_FC);

    embed_k<<<MM, 256>>>(tok, wte, wpe, X);

    for (int i = 0; i < LL; i++) {
        // LN1
        ln_k<<<MM, 256>>>(X, ln1_g + i * EE, ln1_b + i * EE, Hb);
        // QKV = H @ attn_w + attn_b   [2048 x 2304]
        sgemm_k<true, false, false, true><<<dim3(3 * EE / 128, MM / 128), 256>>>(
            Hb, attn_w + (size_t)i * EE * 3 * EE, attn_b + (size_t)i * 3 * EE,
            nullptr, QKV, MM, 3 * EE, EE);
        // attention
        attn_k<<<dim3(SS / 64, HH, BB), 256>>>(QKV, ATT);
        // X = X + ATT @ proj_w + proj_b   [2048 x 768]
        sgemm_k<true, false, true, true><<<dim3(EE / 128, MM / 128), 256>>>(
            ATT, proj_w + (size_t)i * EE * EE, proj_b + (size_t)i * EE,
            X, X, MM, EE, EE);
        // LN2
        ln_k<<<MM, 256>>>(X, ln2_g + i * EE, ln2_b + i * EE, Hb);
        // FC = gelu(H @ fc_w + fc_b)   [2048 x 3072]
        sgemm_k<true, true, false, true><<<dim3(4 * EE / 128, MM / 128), 256>>>(
            Hb, fc_w + (size_t)i * EE * 4 * EE, fc_b + (size_t)i * 4 * EE,
            nullptr, FC, MM, 4 * EE, EE);
        // X = X + FC @ fc2_w + fc2_b   [2048 x 768], K=3072
        sgemm_k<true, false, true, true><<<dim3(EE / 128, MM / 128), 256>>>(
            FC, fc2_w + (size_t)i * 4 * EE * EE, fc2_b + (size_t)i * EE,
            X, X, MM, EE, 4 * EE);
    }

    // final LN
    ln_k<<<MM, 256>>>(X, lnf_g, lnf_b, Hb);
    // logits = H @ lm_w   [2048 x 50257] (N ragged -> scalar B loads)
    sgemm_k<false, false, false, false><<<dim3((VV + 127) / 128, MM / 128), 256>>>(
        Hb, lm_w, nullptr, nullptr, out, MM, VV, EE);
}

// round 2
// speedup vs baseline: 1.0028x; 1.0028x over previous
#include <cuda_runtime.h>
#include <math.h>
#include <stdint.h>

// ---------------------------------------------------------------------------
// GPT-2 small forward:  B=2, S=1024, L=4, H=12, E=768, D=64, V=50257
// ---------------------------------------------------------------------------
#define BB 2
#define SS 1024
#define LL 4
#define HH 12
#define EE 768
#define VV 50257
#define DD 64
#define MM (BB*SS)          // 2048 token rows

// Scratch (device globals: allocation-free rule)
__device__ float g_X  [MM * EE];        // residual stream
__device__ float g_H  [MM * EE];        // LN output
__device__ float g_QKV[MM * 3 * EE];    // qkv
__device__ float g_ATT[MM * EE];        // attention output
__device__ float g_FC [MM * 4 * EE];    // MLP hidden

// ---------------------------------------------------------------------------
// Embedding: x = wte[token] + wpe[s]
// ---------------------------------------------------------------------------
__global__ void embed_k(const int* __restrict__ tok,
                        const float* __restrict__ wte,
                        const float* __restrict__ wpe,
                        float* __restrict__ X)
{
    int row = blockIdx.x;              // 0..2047
    int s   = row & (SS - 1);
    int t   = tok[row];
    const float* we = wte + (size_t)t * EE;
    const float* wp = wpe + (size_t)s * EE;
    float* xr = X + (size_t)row * EE;
    for (int e = threadIdx.x; e < EE; e += blockDim.x)
        xr[e] = we[e] + wp[e];
}

// ---------------------------------------------------------------------------
// LayerNorm: one block (256 threads) per row of 768
// ---------------------------------------------------------------------------
__global__ __launch_bounds__(256) void ln_k(const float* __restrict__ X,
                                            const float* __restrict__ gam,
                                            const float* __restrict__ bet,
                                            float* __restrict__ O)
{
    __shared__ float s1[8], s2[8];
    int row = blockIdx.x, tid = threadIdx.x;
    const float* xr = X + (size_t)row * EE;
    float v[3];
    float sum = 0.f, sq = 0.f;
#pragma unroll
    for (int k = 0; k < 3; k++) {
        v[k] = xr[tid + k * 256];
        sum += v[k];
        sq  += v[k] * v[k];
    }
#pragma unroll
    for (int o = 16; o > 0; o >>= 1) {
        sum += __shfl_xor_sync(0xffffffffu, sum, o);
        sq  += __shfl_xor_sync(0xffffffffu, sq,  o);
    }
    if ((tid & 31) == 0) { s1[tid >> 5] = sum; s2[tid >> 5] = sq; }
    __syncthreads();
    sum = 0.f; sq = 0.f;
#pragma unroll
    for (int i = 0; i < 8; i++) { sum += s1[i]; sq += s2[i]; }
    const float inv_n = 1.0f / (float)EE;
    float mu  = sum * inv_n;
    float var = sq * inv_n - mu * mu;
    float rs  = rsqrtf(var + 1e-5f);
    float* orow = O + (size_t)row * EE;
#pragma unroll
    for (int k = 0; k < 3; k++) {
        int e = tid + k * 256;
        orow[e] = (v[k] - mu) * rs * gam[e] + bet[e];
    }
}

// ---------------------------------------------------------------------------
// SGEMM: C[M,N] = A[M,K] @ B[K,N] (+bias) (+GELU) (+residual)
// 128x128 block tile, BK=8, 8x8 per-thread microtile, 256 threads
// ---------------------------------------------------------------------------
template<bool BIAS, bool GELU, bool RES, bool VECB>
__global__ __launch_bounds__(256) void sgemm_k(const float* __restrict__ A,
                                               const float* __restrict__ Bm,
                                               const float* __restrict__ bias,
                                               const float* __restrict__ res,
                                               float* __restrict__ C,
                                               int M, int N, int K)
{
    const int BK = 8;
    __shared__ float As[BK][128];
    __shared__ float Bs[BK][128];

    int tid = threadIdx.x;
    int bm = blockIdx.y * 128;
    int bn = blockIdx.x * 128;

    int rowA = tid >> 1;            // 0..127
    int colA = (tid & 1) * 4;       // 0 or 4
    int rowB = tid >> 5;            // 0..7
    int colB = (tid & 31) * 4;      // 0..124

    int tr = (tid >> 4) * 8;        // microtile row base
    int tc = (tid & 15) * 8;        // microtile col base

    float acc[8][8];
#pragma unroll
    for (int i = 0; i < 8; i++)
#pragma unroll
        for (int j = 0; j < 8; j++) acc[i][j] = 0.f;

    for (int k0 = 0; k0 < K; k0 += BK) {
        // load A tile (always aligned: K % 4 == 0, M % 128 == 0)
        float4 a4 = *(const float4*)(A + (size_t)(bm + rowA) * K + k0 + colA);
        As[colA + 0][rowA] = a4.x;
        As[colA + 1][rowA] = a4.y;
        As[colA + 2][rowA] = a4.z;
        As[colA + 3][rowA] = a4.w;
        // load B tile
        if (VECB) {
            float4 b4 = *(const float4*)(Bm + (size_t)(k0 + rowB) * N + bn + colB);
            *(float4*)&Bs[rowB][colB] = b4;
        } else {
            const float* brow = Bm + (size_t)(k0 + rowB) * N;
#pragma unroll
            for (int j = 0; j < 4; j++) {
                int n = bn + colB + j;
                Bs[rowB][colB + j] = (n < N) ? brow[n] : 0.f;
            }
        }
        __syncthreads();
#pragma unroll
        for (int kk = 0; kk < BK; kk++) {
            float ra[8], rb[8];
#pragma unroll
            for (int i = 0; i < 8; i++) ra[i] = As[kk][tr + i];
#pragma unroll
            for (int j = 0; j < 8; j++) rb[j] = Bs[kk][tc + j];
#pragma unroll
            for (int i = 0; i < 8; i++)
#pragma unroll
                for (int j = 0; j < 8; j++)
                    acc[i][j] = fmaf(ra[i], rb[j], acc[i][j]);
        }
        __syncthreads();
    }

#pragma unroll
    for (int i = 0; i < 8; i++) {
        int m = bm + tr + i;
#pragma unroll
        for (int j = 0; j < 8; j++) {
            int n = bn + tc + j;
            if (n < N) {
                float vv = acc[i][j];
                if (BIAS) vv += bias[n];
                if (GELU) vv = 0.5f * vv * (1.f + erff(vv * 0.70710678118654752f));
                if (RES)  vv += res[(size_t)m * N + n];
                C[(size_t)m * N + n] = vv;
            }
        }
    }
}

// ---------------------------------------------------------------------------
// Causal attention with online softmax.
// Block = (q_tile=64 queries, head h, batch b); 256 threads.
// K stored transposed in SMEM so score & PV loops vectorize (LDS.128).
// ---------------------------------------------------------------------------
__global__ __launch_bounds__(256) void attn_k(const float* __restrict__ QKV,
                                              float* __restrict__ O)
{
    const int TQ = 64, TK = 32;
    __shared__ float Qs[TQ][DD + 1];      // 64 x 65 (padded, scalar reads)
    __shared__ float Kt[DD][TK];          // 64 x 32 transposed (vector reads)
    __shared__ float Vs[TK][DD];          // 32 x 64 (vector reads)
    __shared__ float Ps[TQ][TK + 1];      // 64 x 33
    __shared__ float red[TQ][4];

    int tid = threadIdx.x;
    int qt = blockIdx.x, h = blockIdx.y, b = blockIdx.z;
    int r  = tid >> 2;                    // query row in tile: 0..63
    int q4 = tid & 3;                     // quad index: 0..3
    int qi = qt * TQ + r;                 // global query index

    const size_t rstride = 3 * EE;
    const float* qkvb = QKV + (size_t)b * SS * rstride;

    // load Q tile
    for (int i = tid; i < TQ * DD; i += 256) {
        int rr = i >> 6, d = i & 63;
        Qs[rr][d] = qkvb[(size_t)(qt * TQ + rr) * rstride + h * DD + d];
    }

    float m = -INFINITY, l = 0.f;
    float o[16];
#pragma unroll
    for (int j = 0; j < 16; j++) o[j] = 0.f;
    const float scale = 0.125f;           // 1/sqrt(64)

    int nkt = (qt + 1) * (TQ / TK);
    for (int kt = 0; kt < nkt; kt++) {
        __syncthreads();                  // protect tiles from prior iter / Q load
        for (int i = tid; i < TK * DD; i += 256) {
            int rr = i >> 6, d = i & 63;
            size_t base = (size_t)(kt * TK + rr) * rstride + h * DD + d;
            Kt[d][rr] = qkvb[EE + base];
            Vs[rr][d] = qkvb[2 * EE + base];
        }
        __syncthreads();

        // --- scores: sc[j] = dot(Q[r], K[c]) over d, c = q4*8+j
        float sc[8];
#pragma unroll
        for (int j = 0; j < 8; j++) sc[j] = 0.f;
#pragma unroll 8
        for (int d = 0; d < DD; d++) {
            float qv = Qs[r][d];
            float4 k0 = *(const float4*)&Kt[d][q4 * 8];
            float4 k1 = *(const float4*)&Kt[d][q4 * 8 + 4];
            sc[0] = fmaf(qv, k0.x, sc[0]);
            sc[1] = fmaf(qv, k0.y, sc[1]);
            sc[2] = fmaf(qv, k0.z, sc[2]);
            sc[3] = fmaf(qv, k0.w, sc[3]);
            sc[4] = fmaf(qv, k1.x, sc[4]);
            sc[5] = fmaf(qv, k1.y, sc[5]);
            sc[6] = fmaf(qv, k1.z, sc[6]);
            sc[7] = fmaf(qv, k1.w, sc[7]);
        }
        float lmax = -INFINITY;
#pragma unroll
        for (int j = 0; j < 8; j++) {
            int kg = kt * TK + q4 * 8 + j;
            sc[j] = (kg <= qi) ? sc[j] * scale : -1e30f;
            lmax = fmaxf(lmax, sc[j]);
        }
        red[r][q4] = lmax;
        __syncthreads();
        float mnew = fmaxf(fmaxf(fmaxf(red[r][0], red[r][1]),
                                 fmaxf(red[r][2], red[r][3])), m);
        __syncthreads();                  // done reading red before reuse

        float lsum = 0.f;
#pragma unroll
        for (int j = 0; j < 8; j++) {
            float p = __expf(sc[j] - mnew);
            Ps[r][q4 * 8 + j] = p;
            lsum += p;
        }
        red[r][q4] = lsum;
        __syncthreads();
        float tsum = red[r][0] + red[r][1] + red[r][2] + red[r][3];
        float fac = __expf(m - mnew);
        l = l * fac + tsum;
        m = mnew;
#pragma unroll
        for (int j = 0; j < 16; j++) o[j] *= fac;

        // --- PV: o[j] += p[c] * V[c][q4*16+j]
#pragma unroll 4
        for (int c = 0; c < TK; c++) {
            float p = Ps[r][c];
            float4 v0 = *(const float4*)&Vs[c][q4 * 16 + 0];
            float4 v1 = *(const float4*)&Vs[c][q4 * 16 + 4];
            float4 v2 = *(const float4*)&Vs[c][q4 * 16 + 8];
            float4 v3 = *(const float4*)&Vs[c][q4 * 16 + 12];
            o[0]  = fmaf(p, v0.x, o[0]);  o[1]  = fmaf(p, v0.y, o[1]);
            o[2]  = fmaf(p, v0.z, o[2]);  o[3]  = fmaf(p, v0.w, o[3]);
            o[4]  = fmaf(p, v1.x, o[4]);  o[5]  = fmaf(p, v1.y, o[5]);
            o[6]  = fmaf(p, v1.z, o[6]);  o[7]  = fmaf(p, v1.w, o[7]);
            o[8]  = fmaf(p, v2.x, o[8]);  o[9]  = fmaf(p, v2.y, o[9]);
            o[10] = fmaf(p, v2.z, o[10]); o[11] = fmaf(p, v2.w, o[11]);
            o[12] = fmaf(p, v3.x, o[12]); o[13] = fmaf(p, v3.y, o[13]);
            o[14] = fmaf(p, v3.z, o[14]); o[15] = fmaf(p, v3.w, o[15]);
        }
    }

    float inv = 1.f / l;
    float* orow = O + ((size_t)b * SS + qi) * EE + h * DD + q4 * 16;
#pragma unroll
    for (int j = 0; j < 16; j++) orow[j] = o[j] * inv;
}

// ---------------------------------------------------------------------------
// Host launcher
// ---------------------------------------------------------------------------
extern "C" void kernel_launch(void* const* d_in, const int* in_sizes, int n_in,
                              void* d_out, int out_size)
{
    const int*   tok    = (const int*)  d_in[0];
    const float* wte    = (const float*)d_in[1];
    const float* wpe    = (const float*)d_in[2];
    const float* ln1_g  = (const float*)d_in[3];
    const float* ln1_b  = (const float*)d_in[4];
    const float* attn_w = (const float*)d_in[5];
    const float* attn_b = (const float*)d_in[6];
    const float* proj_w = (const float*)d_in[7];
    const float* proj_b = (const float*)d_in[8];
    const float* ln2_g  = (const float*)d_in[9];
    const float* ln2_b  = (const float*)d_in[10];
    const float* fc_w   = (const float*)d_in[11];
    const float* fc_b   = (const float*)d_in[12];
    const float* fc2_w  = (const float*)d_in[13];
    const float* fc2_b  = (const float*)d_in[14];
    const float* lnf_g  = (const float*)d_in[15];
    const float* lnf_b  = (const float*)d_in[16];
    const float* lm_w   = (const float*)d_in[17];
    float* out = (float*)d_out;

    float *X, *Hb, *QKV, *ATT, *FC;
    cudaGetSymbolAddress((void**)&X,   g_X);
    cudaGetSymbolAddress((void**)&Hb,  g_H);
    cudaGetSymbolAddress((void**)&QKV, g_QKV);
    cudaGetSymbolAddress((void**)&ATT, g_ATT);
    cudaGetSymbolAddress((void**)&FC,  g_FC);

    embed_k<<<MM, 256>>>(tok, wte, wpe, X);

    for (int i = 0; i < LL; i++) {
        // LN1
        ln_k<<<MM, 256>>>(X, ln1_g + i * EE, ln1_b + i * EE, Hb);
        // QKV = H @ attn_w + attn_b   [2048 x 2304]
        sgemm_k<true, false, false, true><<<dim3(3 * EE / 128, MM / 128), 256>>>(
            Hb, attn_w + (size_t)i * EE * 3 * EE, attn_b + (size_t)i * 3 * EE,
            nullptr, QKV, MM, 3 * EE, EE);
        // attention
        attn_k<<<dim3(SS / 64, HH, BB), 256>>>(QKV, ATT);
        // X = X + ATT @ proj_w + proj_b   [2048 x 768]
        sgemm_k<true, false, true, true><<<dim3(EE / 128, MM / 128), 256>>>(
            ATT, proj_w + (size_t)i * EE * EE, proj_b + (size_t)i * EE,
            X, X, MM, EE, EE);
        // LN2
        ln_k<<<MM, 256>>>(X, ln2_g + i * EE, ln2_b + i * EE, Hb);
        // FC = gelu(H @ fc_w + fc_b)   [2048 x 3072]
        sgemm_k<true, true, false, true><<<dim3(4 * EE / 128, MM / 128), 256>>>(
            Hb, fc_w + (size_t)i * EE * 4 * EE, fc_b + (size_t)i * 4 * EE,
            nullptr, FC, MM, 4 * EE, EE);
        // X = X + FC @ fc2_w + fc2_b   [2048 x 768], K=3072
        sgemm_k<true, false, true, true><<<dim3(EE / 128, MM / 128), 256>>>(
            FC, fc2_w + (size_t)i * 4 * EE * EE, fc2_b + (size_t)i * EE,
            X, X, MM, EE, 4 * EE);
    }

    // final LN
    ln_k<<<MM, 256>>>(X, lnf_g, lnf_b, Hb);
    // logits = H @ lm_w   [2048 x 50257] (N ragged -> scalar B loads)
    sgemm_k<false, false, false, false><<<dim3((VV + 127) / 128, MM / 128), 256>>>(
        Hb, lm_w, nullptr, nullptr, out, MM, VV, EE);
}

// round 3
// speedup vs baseline: 1.0127x; 1.0099x over previous
#include <cuda_runtime.h>
#include <math.h>
#include <stdint.h>

// ---------------------------------------------------------------------------
// GPT-2 small forward:  B=2, S=1024, L=4, H=12, E=768, D=64, V=50257
// ---------------------------------------------------------------------------
#define BB 2
#define SS 1024
#define LL 4
#define HH 12
#define EE 768
#define VV 50257
#define DD 64
#define MM (BB*SS)          // 2048 token rows

// Scratch (device globals: allocation-free rule)
__device__ float g_X  [MM * EE];        // residual stream
__device__ float g_H  [MM * EE];        // LN output
__device__ float g_QKV[MM * 3 * EE];    // qkv
__device__ float g_ATT[MM * EE];        // attention output
__device__ float g_FC [MM * 4 * EE];    // MLP hidden

// ---------------------------------------------------------------------------
// Embedding: x = wte[token] + wpe[s]
// ---------------------------------------------------------------------------
__global__ void embed_k(const int* __restrict__ tok,
                        const float* __restrict__ wte,
                        const float* __restrict__ wpe,
                        float* __restrict__ X)
{
    int row = blockIdx.x;              // 0..2047
    int s   = row & (SS - 1);
    int t   = tok[row];
    const float* we = wte + (size_t)t * EE;
    const float* wp = wpe + (size_t)s * EE;
    float* xr = X + (size_t)row * EE;
    for (int e = threadIdx.x; e < EE; e += blockDim.x)
        xr[e] = we[e] + wp[e];
}

// ---------------------------------------------------------------------------
// LayerNorm: one block (256 threads) per row of 768
// ---------------------------------------------------------------------------
__global__ __launch_bounds__(256) void ln_k(const float* __restrict__ X,
                                            const float* __restrict__ gam,
                                            const float* __restrict__ bet,
                                            float* __restrict__ O)
{
    __shared__ float s1[8], s2[8];
    int row = blockIdx.x, tid = threadIdx.x;
    const float* xr = X + (size_t)row * EE;
    float v[3];
    float sum = 0.f, sq = 0.f;
#pragma unroll
    for (int k = 0; k < 3; k++) {
        v[k] = xr[tid + k * 256];
        sum += v[k];
        sq  += v[k] * v[k];
    }
#pragma unroll
    for (int o = 16; o > 0; o >>= 1) {
        sum += __shfl_xor_sync(0xffffffffu, sum, o);
        sq  += __shfl_xor_sync(0xffffffffu, sq,  o);
    }
    if ((tid & 31) == 0) { s1[tid >> 5] = sum; s2[tid >> 5] = sq; }
    __syncthreads();
    sum = 0.f; sq = 0.f;
#pragma unroll
    for (int i = 0; i < 8; i++) { sum += s1[i]; sq += s2[i]; }
    const float inv_n = 1.0f / (float)EE;
    float mu  = sum * inv_n;
    float var = sq * inv_n - mu * mu;
    float rs  = rsqrtf(var + 1e-5f);
    float* orow = O + (size_t)row * EE;
#pragma unroll
    for (int k = 0; k < 3; k++) {
        int e = tid + k * 256;
        orow[e] = (v[k] - mu) * rs * gam[e] + bet[e];
    }
}

// ---------------------------------------------------------------------------
// SGEMM: C[M,N] = A[M,K] @ B[K,N] (+bias) (+GELU) (+residual)
// 128x128 block tile, BK=8, 8x8 per-thread microtile, 256 threads
// ---------------------------------------------------------------------------
template<bool BIAS, bool GELU, bool RES, bool VECB>
__global__ __launch_bounds__(256) void sgemm_k(const float* __restrict__ A,
                                               const float* __restrict__ Bm,
                                               const float* __restrict__ bias,
                                               const float* __restrict__ res,
                                               float* __restrict__ C,
                                               int M, int N, int K)
{
    const int BK = 8;
    __shared__ float As[BK][128];
    __shared__ float Bs[BK][128];

    int tid = threadIdx.x;
    int bm = blockIdx.y * 128;
    int bn = blockIdx.x * 128;

    int rowA = tid >> 1;            // 0..127
    int colA = (tid & 1) * 4;       // 0 or 4
    int rowB = tid >> 5;            // 0..7
    int colB = (tid & 31) * 4;      // 0..124

    int tr = (tid >> 4) * 8;        // microtile row base
    int tc = (tid & 15) * 8;        // microtile col base

    float acc[8][8];
#pragma unroll
    for (int i = 0; i < 8; i++)
#pragma unroll
        for (int j = 0; j < 8; j++) acc[i][j] = 0.f;

    for (int k0 = 0; k0 < K; k0 += BK) {
        // load A tile (always aligned: K % 4 == 0, M % 128 == 0)
        float4 a4 = *(const float4*)(A + (size_t)(bm + rowA) * K + k0 + colA);
        As[colA + 0][rowA] = a4.x;
        As[colA + 1][rowA] = a4.y;
        As[colA + 2][rowA] = a4.z;
        As[colA + 3][rowA] = a4.w;
        // load B tile
        if (VECB) {
            float4 b4 = *(const float4*)(Bm + (size_t)(k0 + rowB) * N + bn + colB);
            *(float4*)&Bs[rowB][colB] = b4;
        } else {
            const float* brow = Bm + (size_t)(k0 + rowB) * N;
#pragma unroll
            for (int j = 0; j < 4; j++) {
                int n = bn + colB + j;
                Bs[rowB][colB + j] = (n < N) ? brow[n] : 0.f;
            }
        }
        __syncthreads();
#pragma unroll
        for (int kk = 0; kk < BK; kk++) {
            float ra[8], rb[8];
#pragma unroll
            for (int i = 0; i < 8; i++) ra[i] = As[kk][tr + i];
#pragma unroll
            for (int j = 0; j < 8; j++) rb[j] = Bs[kk][tc + j];
#pragma unroll
            for (int i = 0; i < 8; i++)
#pragma unroll
                for (int j = 0; j < 8; j++)
                    acc[i][j] = fmaf(ra[i], rb[j], acc[i][j]);
        }
        __syncthreads();
    }

#pragma unroll
    for (int i = 0; i < 8; i++) {
        int m = bm + tr + i;
#pragma unroll
        for (int j = 0; j < 8; j++) {
            int n = bn + tc + j;
            if (n < N) {
                float vv = acc[i][j];
                if (BIAS) vv += bias[n];
                if (GELU) vv = 0.5f * vv * (1.f + erff(vv * 0.70710678118654752f));
                if (RES)  vv += res[(size_t)m * N + n];
                C[(size_t)m * N + n] = vv;
            }
        }
    }
}

// ---------------------------------------------------------------------------
// Causal attention with online softmax.
// Block = (q_tile=64 queries, head h, batch b); 256 threads.
// K stored transposed in SMEM so score & PV loops vectorize (LDS.128).
// ---------------------------------------------------------------------------
__global__ __launch_bounds__(256) void attn_k(const float* __restrict__ QKV,
                                              float* __restrict__ O)
{
    const int TQ = 64, TK = 32;
    __shared__ float Qs[TQ][DD + 1];      // 64 x 65 (padded, scalar reads)
    __shared__ float Kt[DD][TK];          // 64 x 32 transposed (vector reads)
    __shared__ float Vs[TK][DD];          // 32 x 64 (vector reads)
    __shared__ float Ps[TQ][TK + 1];      // 64 x 33
    __shared__ float red[TQ][4];

    int tid = threadIdx.x;
    int qt = blockIdx.x, h = blockIdx.y, b = blockIdx.z;
    int r  = tid >> 2;                    // query row in tile: 0..63
    int q4 = tid & 3;                     // quad index: 0..3
    int qi = qt * TQ + r;                 // global query index

    const size_t rstride = 3 * EE;
    const float* qkvb = QKV + (size_t)b * SS * rstride;

    // load Q tile
    for (int i = tid; i < TQ * DD; i += 256) {
        int rr = i >> 6, d = i & 63;
        Qs[rr][d] = qkvb[(size_t)(qt * TQ + rr) * rstride + h * DD + d];
    }

    float m = -INFINITY, l = 0.f;
    float o[16];
#pragma unroll
    for (int j = 0; j < 16; j++) o[j] = 0.f;
    const float scale = 0.125f;           // 1/sqrt(64)

    int nkt = (qt + 1) * (TQ / TK);
    for (int kt = 0; kt < nkt; kt++) {
        __syncthreads();                  // protect tiles from prior iter / Q load
        for (int i = tid; i < TK * DD; i += 256) {
            int rr = i >> 6, d = i & 63;
            size_t base = (size_t)(kt * TK + rr) * rstride + h * DD + d;
            Kt[d][rr] = qkvb[EE + base];
            Vs[rr][d] = qkvb[2 * EE + base];
        }
        __syncthreads();

        // --- scores: sc[j] = dot(Q[r], K[c]) over d, c = q4*8+j
        float sc[8];
#pragma unroll
        for (int j = 0; j < 8; j++) sc[j] = 0.f;
#pragma unroll 8
        for (int d = 0; d < DD; d++) {
            float qv = Qs[r][d];
            float4 k0 = *(const float4*)&Kt[d][q4 * 8];
            float4 k1 = *(const float4*)&Kt[d][q4 * 8 + 4];
            sc[0] = fmaf(qv, k0.x, sc[0]);
            sc[1] = fmaf(qv, k0.y, sc[1]);
            sc[2] = fmaf(qv, k0.z, sc[2]);
            sc[3] = fmaf(qv, k0.w, sc[3]);
            sc[4] = fmaf(qv, k1.x, sc[4]);
            sc[5] = fmaf(qv, k1.y, sc[5]);
            sc[6] = fmaf(qv, k1.z, sc[6]);
            sc[7] = fmaf(qv, k1.w, sc[7]);
        }
        float lmax = -INFINITY;
#pragma unroll
        for (int j = 0; j < 8; j++) {
            int kg = kt * TK + q4 * 8 + j;
            sc[j] = (kg <= qi) ? sc[j] * scale : -1e30f;
            lmax = fmaxf(lmax, sc[j]);
        }
        red[r][q4] = lmax;
        __syncthreads();
        float mnew = fmaxf(fmaxf(fmaxf(red[r][0], red[r][1]),
                                 fmaxf(red[r][2], red[r][3])), m);
        __syncthreads();                  // done reading red before reuse

        float lsum = 0.f;
#pragma unroll
        for (int j = 0; j < 8; j++) {
            float p = __expf(sc[j] - mnew);
            Ps[r][q4 * 8 + j] = p;
            lsum += p;
        }
        red[r][q4] = lsum;
        __syncthreads();
        float tsum = red[r][0] + red[r][1] + red[r][2] + red[r][3];
        float fac = __expf(m - mnew);
        l = l * fac + tsum;
        m = mnew;
#pragma unroll
        for (int j = 0; j < 16; j++) o[j] *= fac;

        // --- PV: o[j] += p[c] * V[c][q4*16+j]
#pragma unroll 4
        for (int c = 0; c < TK; c++) {
            float p = Ps[r][c];
            float4 v0 = *(const float4*)&Vs[c][q4 * 16 + 0];
            float4 v1 = *(const float4*)&Vs[c][q4 * 16 + 4];
            float4 v2 = *(const float4*)&Vs[c][q4 * 16 + 8];
            float4 v3 = *(const float4*)&Vs[c][q4 * 16 + 12];
            o[0]  = fmaf(p, v0.x, o[0]);  o[1]  = fmaf(p, v0.y, o[1]);
            o[2]  = fmaf(p, v0.z, o[2]);  o[3]  = fmaf(p, v0.w, o[3]);
            o[4]  = fmaf(p, v1.x, o[4]);  o[5]  = fmaf(p, v1.y, o[5]);
            o[6]  = fmaf(p, v1.z, o[6]);  o[7]  = fmaf(p, v1.w, o[7]);
            o[8]  = fmaf(p, v2.x, o[8]);  o[9]  = fmaf(p, v2.y, o[9]);
            o[10] = fmaf(p, v2.z, o[10]); o[11] = fmaf(p, v2.w, o[11]);
            o[12] = fmaf(p, v3.x, o[12]); o[13] = fmaf(p, v3.y, o[13]);
            o[14] = fmaf(p, v3.z, o[14]); o[15] = fmaf(p, v3.w, o[15]);
        }
    }

    float inv = 1.f / l;
    float* orow = O + ((size_t)b * SS + qi) * EE + h * DD + q4 * 16;
#pragma unroll
    for (int j = 0; j < 16; j++) orow[j] = o[j] * inv;
}

// ---------------------------------------------------------------------------
// Host launcher
// ---------------------------------------------------------------------------
extern "C" void kernel_launch(void* const* d_in, const int* in_sizes, int n_in,
                              void* d_out, int out_size)
{
    const int*   tok    = (const int*)  d_in[0];
    const float* wte    = (const float*)d_in[1];
    const float* wpe    = (const float*)d_in[2];
    const float* ln1_g  = (const float*)d_in[3];
    const float* ln1_b  = (const float*)d_in[4];
    const float* attn_w = (const float*)d_in[5];
    const float* attn_b = (const float*)d_in[6];
    const float* proj_w = (const float*)d_in[7];
    const float* proj_b = (const float*)d_in[8];
    const float* ln2_g  = (const float*)d_in[9];
    const float* ln2_b  = (const float*)d_in[10];
    const float* fc_w   = (const float*)d_in[11];
    const float* fc_b   = (const float*)d_in[12];
    const float* fc2_w  = (const float*)d_in[13];
    const float* fc2_b  = (const float*)d_in[14];
    const float* lnf_g  = (const float*)d_in[15];
    const float* lnf_b  = (const float*)d_in[16];
    const float* lm_w   = (const float*)d_in[17];
    float* out = (float*)d_out;

    float *X, *Hb, *QKV, *ATT, *FC;
    cudaGetSymbolAddress((void**)&X,   g_X);
    cudaGetSymbolAddress((void**)&Hb,  g_H);
    cudaGetSymbolAddress((void**)&QKV, g_QKV);
    cudaGetSymbolAddress((void**)&ATT, g_ATT);
    cudaGetSymbolAddress((void**)&FC,  g_FC);

    embed_k<<<MM, 256>>>(tok, wte, wpe, X);

    for (int i = 0; i < LL; i++) {
        // LN1
        ln_k<<<MM, 256>>>(X, ln1_g + i * EE, ln1_b + i * EE, Hb);
        // QKV = H @ attn_w + attn_b   [2048 x 2304]
        sgemm_k<true, false, false, true><<<dim3(3 * EE / 128, MM / 128), 256>>>(
            Hb, attn_w + (size_t)i * EE * 3 * EE, attn_b + (size_t)i * 3 * EE,
            nullptr, QKV, MM, 3 * EE, EE);
        // attention
        attn_k<<<dim3(SS / 64, HH, BB), 256>>>(QKV, ATT);
        // X = X + ATT @ proj_w + proj_b   [2048 x 768]
        sgemm_k<true, false, true, true><<<dim3(EE / 128, MM / 128), 256>>>(
            ATT, proj_w + (size_t)i * EE * EE, proj_b + (size_t)i * EE,
            X, X, MM, EE, EE);
        // LN2
        ln_k<<<MM, 256>>>(X, ln2_g + i * EE, ln2_b + i * EE, Hb);
        // FC = gelu(H @ fc_w + fc_b)   [2048 x 3072]
        sgemm_k<true, true, false, true><<<dim3(4 * EE / 128, MM / 128), 256>>>(
            Hb, fc_w + (size_t)i * EE * 4 * EE, fc_b + (size_t)i * 4 * EE,
            nullptr, FC, MM, 4 * EE, EE);
        // X = X + FC @ fc2_w + fc2_b   [2048 x 768], K=3072
        sgemm_k<true, false, true, true><<<dim3(EE / 128, MM / 128), 256>>>(
            FC, fc2_w + (size_t)i * 4 * EE * EE, fc2_b + (size_t)i * EE,
            X, X, MM, EE, 4 * EE);
    }

    // final LN
    ln_k<<<MM, 256>>>(X, lnf_g, lnf_b, Hb);
    // logits = H @ lm_w   [2048 x 50257] (N ragged -> scalar B loads)
    sgemm_k<false, false, false, false><<<dim3((VV + 127) / 128, MM / 128), 256>>>(
        Hb, lm_w, nullptr, nullptr, out, MM, VV, EE);
}